// round 13
// baseline (speedup 1.0000x reference)
#include <cuda_runtime.h>
#include <cstdint>

// GatherBlock: out[m, :, :, :] = x[b[m], :, yb[m]*16 : yb[m]*16+16, xb[m]*16 : xb[m]*16+16]
// x: (8, 64, 256, 256) fp32, indices: (1024, 3) int32, out: (1024, 64, 16, 16) fp32.
//
// R13: keep R12's register double-buffering (kernel 23.1 -> 21.6us: loads of
// chunk j+1 in flight while chunk j stores drain), but halve the per-CTA
// serial chain: GRID=2048, 4 chunks per CTA, so the single-wave tail that
// regressed R12's wallclock gets absorbed by ~2 scheduler rounds.
// Keeps: counting-sort tile-ordered schedule, __ldcg reads, __stcs stores.

static constexpr int C = 64;
static constexpr int H = 256;
static constexpr int W = 256;
static constexpr int BH = 16;
static constexpr int BW = 16;
static constexpr int CHW = C * H * W;      // 4194304
static constexpr int HW = H * W;           // 65536
static constexpr int VEC_PER_M = C * BH * BW / 4;       // 4096 float4 per output block
static constexpr int SPLIT = 8;                         // chunks per m
static constexpr int VEC_PER_CHUNK = VEC_PER_M / SPLIT; // 512 float4 per chunk
static constexpr int M_MAX = 1024;
static constexpr int BINS = 2048;                       // 8*16*16 tile ids
static constexpr int TPB = 128;                         // threads per CTA
static constexpr int LPT = VEC_PER_CHUNK / TPB;         // 4 float4 per thread per chunk
static constexpr int GRID = 2048;                       // CTAs (4 chunks each)

__device__ int g_perm[M_MAX];

__global__ __launch_bounds__(M_MAX, 1)
void sort_indices_kernel(const int* __restrict__ idx, int M)
{
    __shared__ unsigned hist[BINS];
    __shared__ unsigned warpsum[32];

    const int t = threadIdx.x;
    const int lane = t & 31;
    const int wid = t >> 5;

    hist[2 * t]     = 0;
    hist[2 * t + 1] = 0;
    __syncthreads();

    int key = 0;
    if (t < M) {
        const int b  = idx[3 * t + 0];
        const int yb = idx[3 * t + 1];
        const int xb = idx[3 * t + 2];
        key = (b << 8) | (yb << 4) | xb;   // 11 bits
        atomicAdd(&hist[key], 1u);
    }
    __syncthreads();

    const unsigned a = hist[2 * t];
    const unsigned bcnt = hist[2 * t + 1];
    const unsigned s = a + bcnt;

    unsigned incl = s;
#pragma unroll
    for (int d = 1; d < 32; d <<= 1) {
        const unsigned n = __shfl_up_sync(0xFFFFFFFFu, incl, d);
        if (lane >= d) incl += n;
    }
    const unsigned thr_excl = incl - s;
    if (lane == 31) warpsum[wid] = incl;
    __syncthreads();

    if (wid == 0) {
        unsigned v = warpsum[lane];
        unsigned pv = v;
#pragma unroll
        for (int d = 1; d < 32; d <<= 1) {
            const unsigned n = __shfl_up_sync(0xFFFFFFFFu, pv, d);
            if (lane >= d) pv += n;
        }
        warpsum[lane] = pv - v;
    }
    __syncthreads();

    const unsigned base = warpsum[wid] + thr_excl;
    hist[2 * t]     = base;
    hist[2 * t + 1] = base + a;
    __syncthreads();

    if (t < M) {
        const unsigned pos = atomicAdd(&hist[key], 1u);
        g_perm[pos] = t;
    }
}

struct ChunkPtrs {
    const float* src;   // tile base in x
    float4* dst;        // block base in out
    int v0;             // first float4 index within the block for this thread
};

__device__ __forceinline__ ChunkPtrs chunk_ptrs(
    const float* __restrict__ x, const int* __restrict__ idx,
    float4* __restrict__ out, int j, int t)
{
    const int m = g_perm[j >> 3];
    const int q = j & 7;
    const int b  = idx[3 * m + 0];
    const int yb = idx[3 * m + 1];
    const int xb = idx[3 * m + 2];
    ChunkPtrs p;
    p.src = x + (size_t)b * CHW + (size_t)(yb * BH) * W + (size_t)(xb * BW);
    p.v0  = q * VEC_PER_CHUNK + t;
    p.dst = out + (size_t)m * VEC_PER_M;
    return p;
}

__device__ __forceinline__ void load_chunk(const ChunkPtrs& p, float4 r[LPT])
{
#pragma unroll
    for (int k = 0; k < LPT; k++) {
        const int v = p.v0 + k * TPB;
        const int c = v >> 6;
        const int i = (v >> 2) & 15;
        const int jj = v & 3;
        const float4* s = reinterpret_cast<const float4*>(
            p.src + (size_t)c * HW + (size_t)i * W) + jj;
        r[k] = __ldcg(s);
    }
}

__device__ __forceinline__ void store_chunk(const ChunkPtrs& p, const float4 r[LPT])
{
#pragma unroll
    for (int k = 0; k < LPT; k++) {
        __stcs(p.dst + p.v0 + k * TPB, r[k]);
    }
}

__global__ __launch_bounds__(TPB, 8)
void gather_block_kernel(const float* __restrict__ x,
                         const int* __restrict__ idx,
                         float4* __restrict__ out)
{
    const int t = threadIdx.x;
    const int total = M_MAX * SPLIT;   // 8192 chunks

    int j0 = blockIdx.x;
    ChunkPtrs p0 = chunk_ptrs(x, idx, out, j0, t);
    float4 a[LPT], b[LPT];
    load_chunk(p0, a);

    for (;;) {
        const int j1 = j0 + GRID;
        if (j1 < total) {
            ChunkPtrs p1 = chunk_ptrs(x, idx, out, j1, t);
            load_chunk(p1, b);          // loads for j1 in flight...
            store_chunk(p0, a);         // ...while j0 stores drain

            const int j2 = j1 + GRID;
            if (j2 < total) {
                ChunkPtrs p2 = chunk_ptrs(x, idx, out, j2, t);
                load_chunk(p2, a);
                store_chunk(p1, b);
                j0 = j2;
                p0 = p2;
                continue;
            }
            store_chunk(p1, b);
            return;
        }
        store_chunk(p0, a);
        return;
    }
}

extern "C" void kernel_launch(void* const* d_in, const int* in_sizes, int n_in,
                              void* d_out, int out_size)
{
    const float* x  = (const float*)d_in[0];
    const int* idx  = (const int*)d_in[1];
    float4* out     = (float4*)d_out;

    const int M = in_sizes[1] / 3;  // 1024
    sort_indices_kernel<<<1, M_MAX>>>(idx, M);
    gather_block_kernel<<<GRID, TPB>>>(x, idx, out);
}

// round 14
// speedup vs baseline: 1.0756x; 1.0756x over previous
#include <cuda_runtime.h>
#include <cstdint>

// GatherBlock: out[m, :, :, :] = x[b[m], :, yb[m]*16 : yb[m]*16+16, xb[m]*16 : xb[m]*16+16]
// x: (8, 64, 256, 256) fp32, indices: (1024, 3) int32, out: (1024, 64, 16, 16) fp32.
//
// R14: DRAM row-buffer locality within a warp. Reads are 64B slivers of 1KB
// DRAM rows (~57% efficiency plateau). After the counting sort, consecutive
// perm entries share (b,yb) w.p. ~7/8 and hence read the SAME 1KB W-rows.
// Each CTA now processes a PAIR of consecutive sorted m's; every thread
// issues the m0/m1 loads for the same (c,row) back-to-back -> temporally
// adjacent same-DRAM-row accesses. Burst structure kept (the double-buffered
// family benched +2.5us worse despite faster ncu time): 128 thr, 8
// front-batched LDG.128, 16KB/CTA, grid 4096, __ldcg reads, __stcs stores.

static constexpr int C = 64;
static constexpr int H = 256;
static constexpr int W = 256;
static constexpr int BH = 16;
static constexpr int BW = 16;
static constexpr int CHW = C * H * W;      // 4194304
static constexpr int HW = H * W;           // 65536
static constexpr int VEC_PER_M = C * BH * BW / 4;     // 4096 float4 per output block
static constexpr int SPLIT = 8;                       // chunks per pair
static constexpr int VEC_PER_CHUNK = VEC_PER_M / SPLIT; // 512 float4 per m per chunk
static constexpr int M_MAX = 1024;
static constexpr int BINS = 2048;                     // 8*16*16 tile ids
static constexpr int TPB = 128;                       // threads per gather CTA
static constexpr int LPM = VEC_PER_CHUNK / TPB;       // 4 float4 per thread per m

__device__ int g_perm[M_MAX];

__global__ __launch_bounds__(M_MAX, 1)
void sort_indices_kernel(const int* __restrict__ idx, int M)
{
    __shared__ unsigned hist[BINS];
    __shared__ unsigned warpsum[32];

    const int t = threadIdx.x;
    const int lane = t & 31;
    const int wid = t >> 5;

    hist[2 * t]     = 0;
    hist[2 * t + 1] = 0;
    __syncthreads();

    int key = 0;
    if (t < M) {
        const int b  = idx[3 * t + 0];
        const int yb = idx[3 * t + 1];
        const int xb = idx[3 * t + 2];
        key = (b << 8) | (yb << 4) | xb;   // 11 bits; (b,yb) groups are contiguous
        atomicAdd(&hist[key], 1u);
    }
    __syncthreads();

    const unsigned a = hist[2 * t];
    const unsigned bcnt = hist[2 * t + 1];
    const unsigned s = a + bcnt;

    unsigned incl = s;
#pragma unroll
    for (int d = 1; d < 32; d <<= 1) {
        const unsigned n = __shfl_up_sync(0xFFFFFFFFu, incl, d);
        if (lane >= d) incl += n;
    }
    const unsigned thr_excl = incl - s;
    if (lane == 31) warpsum[wid] = incl;
    __syncthreads();

    if (wid == 0) {
        unsigned v = warpsum[lane];
        unsigned pv = v;
#pragma unroll
        for (int d = 1; d < 32; d <<= 1) {
            const unsigned n = __shfl_up_sync(0xFFFFFFFFu, pv, d);
            if (lane >= d) pv += n;
        }
        warpsum[lane] = pv - v;
    }
    __syncthreads();

    const unsigned base = warpsum[wid] + thr_excl;
    hist[2 * t]     = base;
    hist[2 * t + 1] = base + a;
    __syncthreads();

    if (t < M) {
        const unsigned pos = atomicAdd(&hist[key], 1u);
        g_perm[pos] = t;
    }
}

__global__ __launch_bounds__(TPB, 8)
void gather_block_kernel(const float* __restrict__ x,
                         const int* __restrict__ idx,
                         float4* __restrict__ out)
{
    const int p = blockIdx.x >> 3;          // pair index (0..511)
    const int q = blockIdx.x & 7;           // which eighth of each block

    const int m0 = g_perm[2 * p];
    const int m1 = g_perm[2 * p + 1];

    const int b0  = idx[3 * m0 + 0];
    const int yb0 = idx[3 * m0 + 1];
    const int xb0 = idx[3 * m0 + 2];
    const int b1  = idx[3 * m1 + 0];
    const int yb1 = idx[3 * m1 + 1];
    const int xb1 = idx[3 * m1 + 2];

    const float* src0 = x + (size_t)b0 * CHW + (size_t)(yb0 * BH) * W + (size_t)(xb0 * BW);
    const float* src1 = x + (size_t)b1 * CHW + (size_t)(yb1 * BH) * W + (size_t)(xb1 * BW);
    float4* dst0 = out + (size_t)m0 * VEC_PER_M;
    float4* dst1 = out + (size_t)m1 * VEC_PER_M;

    const int t = threadIdx.x;
    const int v0 = q * VEC_PER_CHUNK + t;   // first float4 index within each block

    // v in [0, 4096): c = v>>6, row i = (v>>2)&15, j-vector = v&3.
    // Front-batch all 8 loads; m0/m1 loads for the SAME (c,i) are adjacent,
    // hitting the same 1KB DRAM row when the pair shares (b,yb) (~7/8).
    float4 r0[LPM], r1[LPM];
#pragma unroll
    for (int k = 0; k < LPM; k++) {
        const int v = v0 + k * TPB;
        const int c = v >> 6;
        const int i = (v >> 2) & 15;
        const int j = v & 3;
        const size_t off = (size_t)c * HW + (size_t)i * W;
        r0[k] = __ldcg(reinterpret_cast<const float4*>(src0 + off) + j);
        r1[k] = __ldcg(reinterpret_cast<const float4*>(src1 + off) + j);
    }
#pragma unroll
    for (int k = 0; k < LPM; k++) {
        __stcs(dst0 + v0 + k * TPB, r0[k]);
        __stcs(dst1 + v0 + k * TPB, r1[k]);
    }
}

extern "C" void kernel_launch(void* const* d_in, const int* in_sizes, int n_in,
                              void* d_out, int out_size)
{
    const float* x  = (const float*)d_in[0];
    const int* idx  = (const int*)d_in[1];
    float4* out     = (float4*)d_out;

    const int M = in_sizes[1] / 3;  // 1024
    sort_indices_kernel<<<1, M_MAX>>>(idx, M);
    gather_block_kernel<<<(M / 2) * SPLIT, TPB>>>(x, idx, out);
}